// round 1
// baseline (speedup 1.0000x reference)
#include <cuda_runtime.h>
#include <math.h>
#include <stdint.h>

#define N_NODES 100000
#define NFEAT   256
#define HID     32
#define NCOL    64        // 32 z-gate cols + 32 h-gate cols
#define TM      64        // nodes per CTA
#define STRIDE  260       // padded smem row stride (floats): 1040B, 1040%128=16 -> <=2-way conflicts

// Persistent device scratch (no allocations allowed in kernel_launch)
__device__ float g_WcT[NCOL * NFEAT];   // combined gate weights, transposed [n][k]
__device__ float g_bias[NCOL];          // [bz | bh]
__device__ float g_wlin[HID];
__device__ float g_blin;

// Fold W[0,0]+W[1,0] (first 256 rows only; H0=0 kills rows 256..287), stash biases.
__global__ void prep_kernel(const float* __restrict__ Wz, const float* __restrict__ bz,
                            const float* __restrict__ Wh, const float* __restrict__ bh,
                            const float* __restrict__ Wlin, const float* __restrict__ blin)
{
    int idx = blockIdx.x * blockDim.x + threadIdx.x;
    if (idx < NCOL * NFEAT) {
        int n = idx / NFEAT;
        int k = idx % NFEAT;
        const float* W = (n < HID) ? Wz : Wh;   // shape (2,1,288,32) row-major
        int nn = n & (HID - 1);
        float v = W[k * HID + nn] + W[288 * HID + k * HID + nn];
        g_WcT[n * NFEAT + k] = v;
    }
    if (blockIdx.x == 0) {
        int t = threadIdx.x;
        if (t < NCOL) g_bias[t] = (t < HID) ? bz[t] : bh[t - HID];
        if (t < HID)  g_wlin[t] = Wlin[t];
        if (t == 0)   g_blin = blin[0];
    }
}

// packed fp32x2 FMA: d.lo += a.lo*b.lo ; d.hi += a.hi*b.hi  (SASS FFMA2, 2x fp32 rate)
#define FMA2(acc, a, b) \
    asm("fma.rn.f32x2 %0, %1, %2, %0;" : "+l"(acc) : "l"(a), "l"(b))

extern __shared__ float smem[];

__global__ __launch_bounds__(256, 1)
void gcn_main_kernel(const float* __restrict__ x, float* __restrict__ out)
{
    float* sX = smem;                     // [TM][STRIDE]
    float* sW = smem + TM * STRIDE;       // [NCOL][STRIDE], layout [n][k]

    const int tid    = threadIdx.x;
    const int block0 = blockIdx.x * TM;

    // ---- stage combined weights (L2-resident) into smem ----
    for (int idx = tid; idx < NCOL * (NFEAT / 4); idx += 256) {
        int n = idx >> 6, kq = idx & 63;
        float4 v = reinterpret_cast<const float4*>(g_WcT)[n * (NFEAT / 4) + kq];
        *reinterpret_cast<float4*>(sW + n * STRIDE + kq * 4) = v;
    }
    // ---- stage X tile (coalesced; clamp tail block) ----
    for (int idx = tid; idx < TM * (NFEAT / 4); idx += 256) {
        int m = idx >> 6, kq = idx & 63;
        int g = block0 + m;
        if (g >= N_NODES) g = N_NODES - 1;  // tail: compute garbage, never stored
        float4 v = reinterpret_cast<const float4*>(x)[g * (NFEAT / 4) + kq];
        *reinterpret_cast<float4*>(sX + m * STRIDE + kq * 4) = v;
    }
    __syncthreads();

    const int tx = tid & 15;   // -> 4 output cols, n = tx + 16*j
    const int ty = tid >> 4;   // -> 4 nodes,       m = ty*4 + i

    unsigned long long acc[4][4];
#pragma unroll
    for (int i = 0; i < 4; i++)
#pragma unroll
        for (int j = 0; j < 4; j++) acc[i][j] = 0ull;

    const float* xbase = sX + (ty * 4) * STRIDE;
    const float* wbase = sW + tx * STRIDE;

    // K loop, 4 k-values (= 2 f32x2 pairs) per step. Even/odd k accumulate into
    // lo/hi lanes of acc; both operand pairs come directly from 16B smem loads.
#pragma unroll 4
    for (int k = 0; k < NFEAT; k += 4) {
        ulonglong2 xv[4], wv[4];
#pragma unroll
        for (int i = 0; i < 4; i++)
            xv[i] = *reinterpret_cast<const ulonglong2*>(xbase + i * STRIDE + k);
#pragma unroll
        for (int j = 0; j < 4; j++)
            wv[j] = *reinterpret_cast<const ulonglong2*>(wbase + j * 16 * STRIDE + k);

#pragma unroll
        for (int i = 0; i < 4; i++)
#pragma unroll
            for (int j = 0; j < 4; j++)
                FMA2(acc[i][j], xv[i].x, wv[j].x);
#pragma unroll
        for (int i = 0; i < 4; i++)
#pragma unroll
            for (int j = 0; j < 4; j++)
                FMA2(acc[i][j], xv[i].y, wv[j].y);
    }

    __syncthreads();           // everyone done reading sX/sW before reuse

    // collapse k-parity pairs and round-trip through smem (reuse sX region)
    float* sAcc = sX;          // [TM][65], 16.6KB < 66.5KB
#pragma unroll
    for (int i = 0; i < 4; i++) {
#pragma unroll
        for (int j = 0; j < 4; j++) {
            int m = ty * 4 + i;
            int n = tx + 16 * j;
            unsigned long long a = acc[i][j];
            float lo = __uint_as_float((unsigned)(a & 0xFFFFFFFFull));
            float hi = __uint_as_float((unsigned)(a >> 32));
            sAcc[m * 65 + n] = lo + hi;
        }
    }
    __syncthreads();

    // GRU epilogue + Wlin reduction: one thread per node
    if (tid < TM) {
        int g = block0 + tid;
        if (g < N_NODES) {
            const float* row = sAcc + tid * 65;
            float s = g_blin;
#pragma unroll 8
            for (int c = 0; c < HID; c++) {
                float z  = 1.0f / (1.0f + expf(-(row[c] + g_bias[c])));
                float th = tanhf(row[HID + c] + g_bias[HID + c]);
                float h  = (1.0f - z) * th;       // Z*H0 + (1-Z)*H~ with H0=0
                h = fmaxf(h, 0.0f);               // relu
                s = fmaf(h, g_wlin[c], s);
            }
            out[g] = s;
        }
    }
}

extern "C" void kernel_launch(void* const* d_in, const int* in_sizes, int n_in,
                              void* d_out, int out_size)
{
    const float* x    = (const float*)d_in[0];
    // d_in[1]=edge_index, d_in[2]=edge_weight: dead in K=1 DConv
    const float* Wz   = (const float*)d_in[3];
    const float* bz   = (const float*)d_in[4];
    // d_in[5]=Wr, d_in[6]=br: R is dead (H0=0)
    const float* Wh   = (const float*)d_in[7];
    const float* bh   = (const float*)d_in[8];
    const float* Wlin = (const float*)d_in[9];
    const float* blin = (const float*)d_in[10];
    float* out = (float*)d_out;

    prep_kernel<<<64, 256>>>(Wz, bz, Wh, bh, Wlin, blin);

    size_t smem_bytes = (size_t)(TM + NCOL) * STRIDE * sizeof(float);  // 133120
    cudaFuncSetAttribute(gcn_main_kernel,
                         cudaFuncAttributeMaxDynamicSharedMemorySize, (int)smem_bytes);
    int grid = (N_NODES + TM - 1) / TM;  // 1563
    gcn_main_kernel<<<grid, 256, smem_bytes>>>(x, out);
}

// round 2
// speedup vs baseline: 1.8826x; 1.8826x over previous
#include <cuda_runtime.h>
#include <math.h>
#include <stdint.h>

#define N_NODES 100000
#define NFEAT   256
#define HID     32
#define NCOL    64          // 32 z-gate cols + 32 h-gate cols
#define TM      64          // nodes per CTA
#define KC      64          // K chunk
#define NCHUNK  (NFEAT/KC)  // 4
#define SROW    68          // smem row stride in floats (272B: conflict-free 8-lane phases)
#define BUF_FLOATS ((TM + NCOL) * SROW)   // 8704 floats = 34816 B per buffer

// Persistent device scratch
__device__ float g_WcT[NCOL * NFEAT];   // folded gate weights, [n][k]
__device__ float g_bias[NCOL];          // [bz | bh]
__device__ float g_wlin[HID];
__device__ float g_blin;

__global__ void prep_kernel(const float* __restrict__ Wz, const float* __restrict__ bz,
                            const float* __restrict__ Wh, const float* __restrict__ bh,
                            const float* __restrict__ Wlin, const float* __restrict__ blin)
{
    int idx = blockIdx.x * blockDim.x + threadIdx.x;
    if (idx < NCOL * NFEAT) {
        int n = idx / NFEAT;
        int k = idx % NFEAT;
        const float* W = (n < HID) ? Wz : Wh;   // (2,1,288,32) row-major
        int nn = n & (HID - 1);
        g_WcT[n * NFEAT + k] = W[k * HID + nn] + W[288 * HID + k * HID + nn];
    }
    if (blockIdx.x == 0) {
        int t = threadIdx.x;
        if (t < NCOL) g_bias[t] = (t < HID) ? bz[t] : bh[t - HID];
        if (t < HID)  g_wlin[t] = Wlin[t];
        if (t == 0)   g_blin = blin[0];
    }
}

// packed fp32x2 FMA (SASS FFMA2): 2 fp32 MACs per instr
#define FMA2(acc, a, b) \
    asm("fma.rn.f32x2 %0, %1, %2, %0;" : "+l"(acc) : "l"(a), "l"(b))

__device__ __forceinline__ void cp_async16(uint32_t sdst, const void* gsrc) {
    asm volatile("cp.async.ca.shared.global [%0], [%1], 16;\n" :: "r"(sdst), "l"(gsrc));
}
#define CP_COMMIT() asm volatile("cp.async.commit_group;\n" ::: "memory")
#define CP_WAIT1()  asm volatile("cp.async.wait_group 1;\n" ::: "memory")
#define CP_WAIT0()  asm volatile("cp.async.wait_group 0;\n" ::: "memory")

extern __shared__ float smem[];

// Stage K-chunk c (X tile + W tile) into the given buffer via cp.async.
__device__ __forceinline__ void stage_chunk(int c, float* buf, const float* __restrict__ x,
                                            int block0, int tid)
{
    uint32_t sbase = (uint32_t)__cvta_generic_to_shared(buf);
    // X chunk: TM rows x KC floats = 1024 x 16B
#pragma unroll
    for (int t = 0; t < 4; t++) {
        int idx = tid + t * 256;
        int m = idx >> 4, c16 = idx & 15;
        int g = block0 + m;
        if (g >= N_NODES) g = N_NODES - 1;     // tail clamp: garbage computed, never stored
        const float* src = x + (size_t)g * NFEAT + c * KC + c16 * 4;
        cp_async16(sbase + (uint32_t)(m * SROW + c16 * 4) * 4u, src);
    }
    // W chunk: NCOL rows x KC floats
    uint32_t wbase = sbase + TM * SROW * 4u;
#pragma unroll
    for (int t = 0; t < 4; t++) {
        int idx = tid + t * 256;
        int n = idx >> 4, c16 = idx & 15;
        const float* src = g_WcT + n * NFEAT + c * KC + c16 * 4;
        cp_async16(wbase + (uint32_t)(n * SROW + c16 * 4) * 4u, src);
    }
}

__global__ __launch_bounds__(256, 3)
void gcn_main_kernel(const float* __restrict__ x, float* __restrict__ out)
{
    const int tid    = threadIdx.x;
    const int block0 = blockIdx.x * TM;
    const int tx = tid & 31;     // cols: n = tx, tx+32
    const int ty = tid >> 5;     // nodes: m = ty*8 + i  (xv loads warp-uniform)

    stage_chunk(0, smem, x, block0, tid);
    CP_COMMIT();

    unsigned long long acc[8][2];
#pragma unroll
    for (int i = 0; i < 8; i++) { acc[i][0] = 0ull; acc[i][1] = 0ull; }

    for (int c = 0; c < NCHUNK; c++) {
        float* buf = smem + (c & 1) * BUF_FLOATS;
        __syncthreads();   // all threads done reading the buffer about to be overwritten
        if (c + 1 < NCHUNK) {
            stage_chunk(c + 1, smem + ((c + 1) & 1) * BUF_FLOATS, x, block0, tid);
            CP_COMMIT();
            CP_WAIT1();    // chunk c's group complete
        } else {
            CP_WAIT0();
        }
        __syncthreads();

        const float* pX = buf + ty * 8 * SROW;
        const float* pW = buf + TM * SROW + tx * SROW;

#pragma unroll 4
        for (int k = 0; k < KC; k += 4) {
            ulonglong2 wv0 = *reinterpret_cast<const ulonglong2*>(pW + k);
            ulonglong2 wv1 = *reinterpret_cast<const ulonglong2*>(pW + 32 * SROW + k);
#pragma unroll
            for (int i = 0; i < 8; i++) {
                ulonglong2 xv = *reinterpret_cast<const ulonglong2*>(pX + i * SROW + k);
                FMA2(acc[i][0], xv.x, wv0.x);
                FMA2(acc[i][0], xv.y, wv0.y);
                FMA2(acc[i][1], xv.x, wv1.x);
                FMA2(acc[i][1], xv.y, wv1.y);
            }
        }
    }

    __syncthreads();
    // collapse k-parity lanes, round-trip through smem (reuse buffer 0)
    float* sAcc = smem;   // [TM][65]
#pragma unroll
    for (int i = 0; i < 8; i++) {
#pragma unroll
        for (int j = 0; j < 2; j++) {
            int m = ty * 8 + i;
            int n = tx + 32 * j;
            unsigned long long a = acc[i][j];
            float lo = __uint_as_float((unsigned)(a & 0xFFFFFFFFull));
            float hi = __uint_as_float((unsigned)(a >> 32));
            sAcc[m * 65 + n] = lo + hi;
        }
    }
    __syncthreads();

    // GRU epilogue + Wlin dot: one thread per node
    if (tid < TM) {
        int g = block0 + tid;
        if (g < N_NODES) {
            const float* row = sAcc + tid * 65;
            float s = g_blin;
#pragma unroll 8
            for (int c = 0; c < HID; c++) {
                float z  = 1.0f / (1.0f + expf(-(row[c] + g_bias[c])));
                float th = tanhf(row[HID + c] + g_bias[HID + c]);
                float h  = fmaxf((1.0f - z) * th, 0.0f);   // H0=0 GRU + relu
                s = fmaf(h, g_wlin[c], s);
            }
            out[g] = s;
        }
    }
}

extern "C" void kernel_launch(void* const* d_in, const int* in_sizes, int n_in,
                              void* d_out, int out_size)
{
    const float* x    = (const float*)d_in[0];
    const float* Wz   = (const float*)d_in[3];
    const float* bz   = (const float*)d_in[4];
    const float* Wh   = (const float*)d_in[7];
    const float* bh   = (const float*)d_in[8];
    const float* Wlin = (const float*)d_in[9];
    const float* blin = (const float*)d_in[10];
    float* out = (float*)d_out;

    prep_kernel<<<64, 256>>>(Wz, bz, Wh, bh, Wlin, blin);

    size_t smem_bytes = 2u * BUF_FLOATS * sizeof(float);   // 69632 B
    cudaFuncSetAttribute(gcn_main_kernel,
                         cudaFuncAttributeMaxDynamicSharedMemorySize, (int)smem_bytes);
    int grid = (N_NODES + TM - 1) / TM;  // 1563
    gcn_main_kernel<<<grid, 256, smem_bytes>>>(x, out);
}

// round 4
// speedup vs baseline: 4.3975x; 2.3358x over previous
#include <cuda_runtime.h>
#include <cuda_bf16.h>
#include <math.h>
#include <stdint.h>

#define N_NODES 100000
#define NFEAT   256
#define HID     32
#define NCOL    64
#define TILE_M  128
#define NT      782          // ceil(100000/128)

// B smem: 64 rows x 264 bf16 (528B padded rows, conflict-free ldmatrix phases)
#define BROW_B   528
#define B_BYTES  (NCOL * BROW_B)     // 33792
#define B_HI_OFF 0
#define B_LO_OFF B_BYTES
#define BIAS_OFF (2 * B_BYTES)             // 64 f32
#define WLIN_OFF (BIAS_OFF + 256)          // 32 f32
#define BLIN_OFF (WLIN_OFF + 128)
#define SMEM_TOTAL (BLIN_OFF + 16)         // ~67.9 KB

// persistent device scratch (prep output)
__device__ __nv_bfloat16 g_Whi[NCOL * NFEAT];
__device__ __nv_bfloat16 g_Wlo[NCOL * NFEAT];
__device__ float g_bias[NCOL];
__device__ float g_wlin[HID];
__device__ float g_blin;

__global__ void prep_kernel(const float* __restrict__ Wz, const float* __restrict__ bz,
                            const float* __restrict__ Wh, const float* __restrict__ bh,
                            const float* __restrict__ Wlin, const float* __restrict__ blin)
{
    int idx = blockIdx.x * blockDim.x + threadIdx.x;
    if (idx < NCOL * NFEAT) {
        int n = idx / NFEAT, k = idx % NFEAT;
        const float* W = (n < HID) ? Wz : Wh;         // (2,1,288,32) row-major
        int nn = n & (HID - 1);
        float w = W[k * HID + nn] + W[288 * HID + k * HID + nn];
        __nv_bfloat16 hi = __float2bfloat16(w);
        g_Whi[idx] = hi;
        g_Wlo[idx] = __float2bfloat16(w - __bfloat162float(hi));
    }
    if (blockIdx.x == 0) {
        int t = threadIdx.x;
        if (t < NCOL) g_bias[t] = (t < HID) ? bz[t] : bh[t - HID];
        if (t < HID)  g_wlin[t] = Wlin[t];
        if (t == 0)   g_blin = blin[0];
    }
}

// ---------- helpers ----------
#define MMA(acc, a, b0, b1) \
    asm("mma.sync.aligned.m16n8k16.row.col.f32.bf16.bf16.f32 " \
        "{%0,%1,%2,%3}, {%4,%5,%6,%7}, {%8,%9}, {%0,%1,%2,%3};" \
        : "+f"((acc)[0]), "+f"((acc)[1]), "+f"((acc)[2]), "+f"((acc)[3]) \
        : "r"((a)[0]), "r"((a)[1]), "r"((a)[2]), "r"((a)[3]), "r"(b0), "r"(b1))

#define LDM4(r, addr) \
    asm("ldmatrix.sync.aligned.m8n8.x4.shared.b16 {%0,%1,%2,%3}, [%4];" \
        : "=r"((r)[0]), "=r"((r)[1]), "=r"((r)[2]), "=r"((r)[3]) : "r"(addr))

// split float2 into packed bf16 hi (exact round) and bf16 of residual
#define CVTHILO(v, h, l) do { \
    asm("cvt.rn.bf16x2.f32 %0, %1, %2;" : "=r"(h) : "f"((v).y), "f"((v).x)); \
    float _rx = (v).x - __uint_as_float((h) << 16); \
    float _ry = (v).y - __uint_as_float((h) & 0xffff0000u); \
    asm("cvt.rn.bf16x2.f32 %0, %1, %2;" : "=r"(l) : "f"(_ry), "f"(_rx)); \
} while (0)

extern __shared__ __align__(128) char smem[];

__global__ __launch_bounds__(256, 2)
void gcn_hmma_kernel(const float* __restrict__ x, float* __restrict__ out)
{
    const int tid  = threadIdx.x;
    const uint32_t sbase = (uint32_t)__cvta_generic_to_shared(smem);

    // ---- stage B hi/lo into padded smem rows (8B chunks) ----
    {
        const uint2* whi = reinterpret_cast<const uint2*>(g_Whi);
        const uint2* wlo = reinterpret_cast<const uint2*>(g_Wlo);
#pragma unroll
        for (int i = 0; i < 16; i++) {
            int idx = tid + i * 256;          // 0..4095
            int n = idx >> 6, c = idx & 63;   // 64 chunks of 4 bf16 per row
            *reinterpret_cast<uint2*>(smem + B_HI_OFF + n * BROW_B + c * 8) = whi[idx];
            *reinterpret_cast<uint2*>(smem + B_LO_OFF + n * BROW_B + c * 8) = wlo[idx];
        }
    }
    if (tid < NCOL) reinterpret_cast<float*>(smem + BIAS_OFF)[tid] = g_bias[tid];
    if (tid < HID)  reinterpret_cast<float*>(smem + WLIN_OFF)[tid] = g_wlin[tid];
    if (tid == 0)   reinterpret_cast<float*>(smem + BLIN_OFF)[0] = g_blin;
    __syncthreads();

    const int warp = tid >> 5, lane = tid & 31;
    const int g = lane >> 2, t = lane & 3;

    const int nodeBase = blockIdx.x * TILE_M + warp * 16;
    const int r0 = nodeBase + g, r1 = r0 + 8;
    const int cr0 = (r0 < N_NODES) ? r0 : (N_NODES - 1);
    const int cr1 = (r1 < N_NODES) ? r1 : (N_NODES - 1);
    const float2* p0 = reinterpret_cast<const float2*>(x) + (size_t)cr0 * 128;
    const float2* p1 = reinterpret_cast<const float2*>(x) + (size_t)cr1 * 128;

    // ldmatrix per-lane address components (matrix mi = lane>>3, row = lane&7)
    const int lm_n = ((lane >> 4) & 1) * 8 + (lane & 7);  // n within 16-row block
    const int lm_k = ((lane >> 3) & 1) * 8;               // k offset 0/8
    const uint32_t lmhi = sbase + B_HI_OFF + lm_n * BROW_B + lm_k * 2;

    float acc[8][4];
#pragma unroll
    for (int i = 0; i < 8; i++)
#pragma unroll
        for (int j = 0; j < 4; j++) acc[i][j] = 0.0f;

#pragma unroll 2
    for (int ks = 0; ks < 16; ks++) {
        // A fragments: rows {g, g+8}, cols {2t,2t+1, 2t+8,2t+9} at k = ks*16
        float2 v00 = __ldg(p0 + ks * 8 + t);
        float2 v10 = __ldg(p1 + ks * 8 + t);
        float2 v01 = __ldg(p0 + ks * 8 + t + 4);
        float2 v11 = __ldg(p1 + ks * 8 + t + 4);

        uint32_t ah[4], al[4];
        CVTHILO(v00, ah[0], al[0]);
        CVTHILO(v10, ah[1], al[1]);
        CVTHILO(v01, ah[2], al[2]);
        CVTHILO(v11, ah[3], al[3]);

#pragma unroll
        for (int nt2 = 0; nt2 < 4; nt2++) {
            uint32_t ba = lmhi + nt2 * (16 * BROW_B) + ks * 32;
            uint32_t bh[4], bl[4];
            LDM4(bh, ba);
            LDM4(bl, ba + B_BYTES);
            // hi*hi + lo*hi + hi*lo (lo*lo dropped, ~2^-18)
            MMA(acc[2 * nt2],     ah, bh[0], bh[1]);
            MMA(acc[2 * nt2],     al, bh[0], bh[1]);
            MMA(acc[2 * nt2],     ah, bl[0], bl[1]);
            MMA(acc[2 * nt2 + 1], ah, bh[2], bh[3]);
            MMA(acc[2 * nt2 + 1], al, bh[2], bh[3]);
            MMA(acc[2 * nt2 + 1], ah, bl[2], bl[3]);
        }
    }

    // ---- epilogue: fully register/shuffle based ----
    const float* sBias = reinterpret_cast<const float*>(smem + BIAS_OFF);
    const float* sWlin = reinterpret_cast<const float*>(smem + WLIN_OFF);
    const float  blin  = reinterpret_cast<const float*>(smem + BLIN_OFF)[0];

#pragma unroll
    for (int row = 0; row < 2; row++) {
        float s = 0.0f;
#pragma unroll
        for (int nt = 0; nt < 4; nt++) {
#pragma unroll
            for (int j = 0; j < 2; j++) {
                int c = nt * 8 + 2 * t + j;
                float zv = acc[nt][row * 2 + j]     + sBias[c];
                float hv = acc[nt + 4][row * 2 + j] + sBias[HID + c];
                float z  = 1.0f / (1.0f + __expf(-zv));
                float th = tanhf(hv);
                float h  = fmaxf((1.0f - z) * th, 0.0f);
                s = fmaf(h, sWlin[c], s);
            }
        }
        s += __shfl_xor_sync(0xffffffffu, s, 1);
        s += __shfl_xor_sync(0xffffffffu, s, 2);
        int node = row ? r1 : r0;
        if (t == 0 && node < N_NODES) out[node] = s + blin;
    }
}

extern "C" void kernel_launch(void* const* d_in, const int* in_sizes, int n_in,
                              void* d_out, int out_size)
{
    const float* x    = (const float*)d_in[0];
    const float* Wz   = (const float*)d_in[3];
    const float* bz   = (const float*)d_in[4];
    const float* Wh   = (const float*)d_in[7];
    const float* bh   = (const float*)d_in[8];
    const float* Wlin = (const float*)d_in[9];
    const float* blin = (const float*)d_in[10];
    float* out = (float*)d_out;

    prep_kernel<<<64, 256>>>(Wz, bz, Wh, bh, Wlin, blin);

    cudaFuncSetAttribute(gcn_hmma_kernel,
                         cudaFuncAttributeMaxDynamicSharedMemorySize, SMEM_TOTAL);
    gcn_hmma_kernel<<<NT, 256, SMEM_TOTAL>>>(x, out);
}

// round 5
// speedup vs baseline: 4.4836x; 1.0196x over previous
#include <cuda_runtime.h>
#include <cuda_bf16.h>
#include <math.h>
#include <stdint.h>

#define N_NODES 100000
#define NFEAT   256
#define HID     32
#define NCOL    64
#define TILE_M  128
#define NT      782          // ceil(100000/128)

// B smem: 64 rows x 264 bf16 (528B padded rows, conflict-free ldmatrix phases)
#define BROW_B   528
#define B_BYTES  (NCOL * BROW_B)     // 33792
#define B_HI_OFF 0
#define B_LO_OFF B_BYTES
#define BIAS_OFF (2 * B_BYTES)             // 64 f32
#define WLIN_OFF (BIAS_OFF + 256)          // 32 f32
#define BLIN_OFF (WLIN_OFF + 128)
#define SMEM_TOTAL (BLIN_OFF + 16)         // ~67.9 KB

// persistent device scratch (prep output; W stored K-PERMUTED within 16-blocks)
__device__ __nv_bfloat16 g_Whi[NCOL * NFEAT];
__device__ __nv_bfloat16 g_Wlo[NCOL * NFEAT];
__device__ float g_bias[NCOL];
__device__ float g_wlin[HID];
__device__ float g_blin;

// logical fragment position p -> physical k within a 16-block, so that lane t's
// float4 at physical cols 4t..4t+3 lands at logical (2t,2t+1,2t+8,2t+9)
__device__ __forceinline__ int kperm(int p) {
    return (p < 8) ? (4 * (p >> 1) + (p & 1))
                   : (4 * ((p - 8) >> 1) + 2 + (p & 1));
}

__global__ void prep_kernel(const float* __restrict__ Wz, const float* __restrict__ bz,
                            const float* __restrict__ Wh, const float* __restrict__ bh,
                            const float* __restrict__ Wlin, const float* __restrict__ blin)
{
    int idx = blockIdx.x * blockDim.x + threadIdx.x;
    if (idx < NCOL * NFEAT) {
        int n = idx / NFEAT, k = idx % NFEAT;               // k = logical position
        int kp = (k & ~15) | kperm(k & 15);                 // physical source col
        const float* W = (n < HID) ? Wz : Wh;               // (2,1,288,32) row-major
        int nn = n & (HID - 1);
        float w = W[kp * HID + nn] + W[288 * HID + kp * HID + nn];
        __nv_bfloat16 hi = __float2bfloat16(w);
        g_Whi[idx] = hi;
        g_Wlo[idx] = __float2bfloat16(w - __bfloat162float(hi));
    }
    if (blockIdx.x == 0) {
        int t = threadIdx.x;
        if (t < NCOL) g_bias[t] = (t < HID) ? bz[t] : bh[t - HID];
        if (t < HID)  g_wlin[t] = Wlin[t];
        if (t == 0)   g_blin = blin[0];
    }
}

// ---------- helpers ----------
#define MMA(acc, a, b0, b1) \
    asm("mma.sync.aligned.m16n8k16.row.col.f32.bf16.bf16.f32 " \
        "{%0,%1,%2,%3}, {%4,%5,%6,%7}, {%8,%9}, {%0,%1,%2,%3};" \
        : "+f"((acc)[0]), "+f"((acc)[1]), "+f"((acc)[2]), "+f"((acc)[3]) \
        : "r"((a)[0]), "r"((a)[1]), "r"((a)[2]), "r"((a)[3]), "r"(b0), "r"(b1))

#define LDM4(r, addr) \
    asm("ldmatrix.sync.aligned.m8n8.x4.shared.b16 {%0,%1,%2,%3}, [%4];" \
        : "=r"((r)[0]), "=r"((r)[1]), "=r"((r)[2]), "=r"((r)[3]) : "r"(addr))

// pack (fx,fy) -> bf16x2 hi (exact round) and bf16x2 of residual
#define CVTHILO2(fx, fy, h, l) do { \
    asm("cvt.rn.bf16x2.f32 %0, %1, %2;" : "=r"(h) : "f"(fy), "f"(fx)); \
    float _rx = (fx) - __uint_as_float((h) << 16); \
    float _ry = (fy) - __uint_as_float((h) & 0xffff0000u); \
    asm("cvt.rn.bf16x2.f32 %0, %1, %2;" : "=r"(l) : "f"(_ry), "f"(_rx)); \
} while (0)

__device__ __forceinline__ float fast_tanh(float v) {
    // tanh(v) = 1 - 2/(exp(2v)+1)
    return 1.0f - 2.0f / (__expf(2.0f * v) + 1.0f);
}

extern __shared__ __align__(128) char smem[];

__global__ __launch_bounds__(256, 2)
void gcn_hmma_kernel(const float* __restrict__ x, float* __restrict__ out)
{
    const int tid  = threadIdx.x;
    const uint32_t sbase = (uint32_t)__cvta_generic_to_shared(smem);

    // ---- stage B hi/lo into padded smem rows (8B chunks) ----
    {
        const uint2* whi = reinterpret_cast<const uint2*>(g_Whi);
        const uint2* wlo = reinterpret_cast<const uint2*>(g_Wlo);
#pragma unroll
        for (int i = 0; i < 16; i++) {
            int idx = tid + i * 256;          // 0..4095
            int n = idx >> 6, c = idx & 63;   // 64 chunks of 4 bf16 per row
            *reinterpret_cast<uint2*>(smem + B_HI_OFF + n * BROW_B + c * 8) = whi[idx];
            *reinterpret_cast<uint2*>(smem + B_LO_OFF + n * BROW_B + c * 8) = wlo[idx];
        }
    }
    if (tid < NCOL) reinterpret_cast<float*>(smem + BIAS_OFF)[tid] = g_bias[tid];
    if (tid < HID)  reinterpret_cast<float*>(smem + WLIN_OFF)[tid] = g_wlin[tid];
    if (tid == 0)   reinterpret_cast<float*>(smem + BLIN_OFF)[0] = g_blin;
    __syncthreads();

    const int warp = tid >> 5, lane = tid & 31;
    const int g = lane >> 2, t = lane & 3;

    const int nodeBase = blockIdx.x * TILE_M + warp * 16;
    const int r0 = nodeBase + g, r1 = r0 + 8;
    const int cr0 = (r0 < N_NODES) ? r0 : (N_NODES - 1);
    const int cr1 = (r1 < N_NODES) ? r1 : (N_NODES - 1);
    // one float4 per row per k16-step: physical cols 4t..4t+3 of that block
    const float4* p0 = reinterpret_cast<const float4*>(x) + (size_t)cr0 * 64 + t;
    const float4* p1 = reinterpret_cast<const float4*>(x) + (size_t)cr1 * 64 + t;

    // ldmatrix per-lane address (logical layout; matches permuted-stored W)
    const int lm_n = ((lane >> 4) & 1) * 8 + (lane & 7);
    const int lm_k = ((lane >> 3) & 1) * 8;
    const uint32_t lmhi = sbase + B_HI_OFF + lm_n * BROW_B + lm_k * 2;

    float acc[8][4];
#pragma unroll
    for (int i = 0; i < 8; i++)
#pragma unroll
        for (int j = 0; j < 4; j++) acc[i][j] = 0.0f;

#pragma unroll 4
    for (int ks = 0; ks < 16; ks++) {
        float4 v0 = __ldg(p0 + ks * 4);   // row r0: logical k-pairs (2t,2t+1),(2t+8,2t+9)
        float4 v1 = __ldg(p1 + ks * 4);   // row r1

        uint32_t ah[4], al[4];
        CVTHILO2(v0.x, v0.y, ah[0], al[0]);
        CVTHILO2(v1.x, v1.y, ah[1], al[1]);
        CVTHILO2(v0.z, v0.w, ah[2], al[2]);
        CVTHILO2(v1.z, v1.w, ah[3], al[3]);

#pragma unroll
        for (int nt2 = 0; nt2 < 4; nt2++) {
            uint32_t ba = lmhi + nt2 * (16 * BROW_B) + ks * 32;
            uint32_t bh[4], bl[4];
            LDM4(bh, ba);
            LDM4(bl, ba + B_BYTES);
            // hi*hi + lo*hi + hi*lo (lo*lo dropped, ~2^-18)
            MMA(acc[2 * nt2],     ah, bh[0], bh[1]);
            MMA(acc[2 * nt2],     al, bh[0], bh[1]);
            MMA(acc[2 * nt2],     ah, bl[0], bl[1]);
            MMA(acc[2 * nt2 + 1], ah, bh[2], bh[3]);
            MMA(acc[2 * nt2 + 1], al, bh[2], bh[3]);
            MMA(acc[2 * nt2 + 1], ah, bl[2], bl[3]);
        }
    }

    // ---- epilogue: fully register/shuffle based ----
    const float* sBias = reinterpret_cast<const float*>(smem + BIAS_OFF);
    const float* sWlin = reinterpret_cast<const float*>(smem + WLIN_OFF);
    const float  blin  = reinterpret_cast<const float*>(smem + BLIN_OFF)[0];

#pragma unroll
    for (int row = 0; row < 2; row++) {
        float s = 0.0f;
#pragma unroll
        for (int nt = 0; nt < 4; nt++) {
#pragma unroll
            for (int j = 0; j < 2; j++) {
                int c = nt * 8 + 2 * t + j;
                float zv = acc[nt][row * 2 + j]     + sBias[c];
                float hv = acc[nt + 4][row * 2 + j] + sBias[HID + c];
                float z  = 1.0f / (1.0f + __expf(-zv));
                float th = fast_tanh(hv);
                float h  = fmaxf((1.0f - z) * th, 0.0f);
                s = fmaf(h, sWlin[c], s);
            }
        }
        s += __shfl_xor_sync(0xffffffffu, s, 1);
        s += __shfl_xor_sync(0xffffffffu, s, 2);
        int node = row ? r1 : r0;
        if (t == 0 && node < N_NODES) out[node] = s + blin;
    }
}

extern "C" void kernel_launch(void* const* d_in, const int* in_sizes, int n_in,
                              void* d_out, int out_size)
{
    const float* x    = (const float*)d_in[0];
    const float* Wz   = (const float*)d_in[3];
    const float* bz   = (const float*)d_in[4];
    const float* Wh   = (const float*)d_in[7];
    const float* bh   = (const float*)d_in[8];
    const float* Wlin = (const float*)d_in[9];
    const float* blin = (const float*)d_in[10];
    float* out = (float*)d_out;

    prep_kernel<<<64, 256>>>(Wz, bz, Wh, bh, Wlin, blin);

    cudaFuncSetAttribute(gcn_hmma_kernel,
                         cudaFuncAttributeMaxDynamicSharedMemorySize, SMEM_TOTAL);
    gcn_hmma_kernel<<<NT, 256, SMEM_TOTAL>>>(x, out);
}

// round 6
// speedup vs baseline: 4.7142x; 1.0514x over previous
#include <cuda_runtime.h>
#include <cuda_bf16.h>
#include <math.h>
#include <stdint.h>

#define N_NODES 100000
#define NFEAT   256
#define HID     32
#define NCOL    64
#define TILE_M  128
#define NT      782          // ceil(100000/128)

// B smem: 64 rows x 264 bf16 (528B padded rows, conflict-free ldmatrix phases)
#define BROW_B   528
#define B_BYTES  (NCOL * BROW_B)     // 33792
#define B_HI_OFF 0
#define B_LO_OFF B_BYTES
#define BIAS_OFF (2 * B_BYTES)             // 64 f32
#define WLIN_OFF (BIAS_OFF + 256)          // 32 f32
#define BLIN_OFF (WLIN_OFF + 128)
#define SMEM_TOTAL (BLIN_OFF + 16)         // ~67.9 KB

// persistent device scratch (prep output; W stored K-PERMUTED within 16-blocks)
__device__ __nv_bfloat16 g_Whi[NCOL * NFEAT];
__device__ __nv_bfloat16 g_Wlo[NCOL * NFEAT];
__device__ float g_bias[NCOL];
__device__ float g_wlin[HID];
__device__ float g_blin;

// logical fragment position p -> physical k within a 16-block, so that lane t's
// float4 at physical cols 4t..4t+3 lands at logical (2t,2t+1,2t+8,2t+9)
__device__ __forceinline__ int kperm(int p) {
    return (p < 8) ? (4 * (p >> 1) + (p & 1))
                   : (4 * ((p - 8) >> 1) + 2 + (p & 1));
}

__global__ void prep_kernel(const float* __restrict__ Wz, const float* __restrict__ bz,
                            const float* __restrict__ Wh, const float* __restrict__ bh,
                            const float* __restrict__ Wlin, const float* __restrict__ blin)
{
    int idx = blockIdx.x * blockDim.x + threadIdx.x;
    if (idx < NCOL * NFEAT) {
        int n = idx / NFEAT, k = idx % NFEAT;               // k = logical position
        int kp = (k & ~15) | kperm(k & 15);                 // physical source col
        const float* W = (n < HID) ? Wz : Wh;               // (2,1,288,32) row-major
        int nn = n & (HID - 1);
        float w = W[kp * HID + nn] + W[288 * HID + kp * HID + nn];
        __nv_bfloat16 hi = __float2bfloat16(w);
        g_Whi[idx] = hi;
        g_Wlo[idx] = __float2bfloat16(w - __bfloat162float(hi));
    }
    if (blockIdx.x == 0) {
        int t = threadIdx.x;
        if (t < NCOL) g_bias[t] = (t < HID) ? bz[t] : bh[t - HID];
        if (t < HID)  g_wlin[t] = Wlin[t];
        if (t == 0)   g_blin = blin[0];
    }
}

// ---------- helpers ----------
#define MMA(acc, a, b0, b1) \
    asm("mma.sync.aligned.m16n8k16.row.col.f32.bf16.bf16.f32 " \
        "{%0,%1,%2,%3}, {%4,%5,%6,%7}, {%8,%9}, {%0,%1,%2,%3};" \
        : "+f"((acc)[0]), "+f"((acc)[1]), "+f"((acc)[2]), "+f"((acc)[3]) \
        : "r"((a)[0]), "r"((a)[1]), "r"((a)[2]), "r"((a)[3]), "r"(b0), "r"(b1))

#define LDM4(r, addr) \
    asm("ldmatrix.sync.aligned.m8n8.x4.shared.b16 {%0,%1,%2,%3}, [%4];" \
        : "=r"((r)[0]), "=r"((r)[1]), "=r"((r)[2]), "=r"((r)[3]) : "r"(addr))

// pack (fx,fy) -> bf16x2 hi (exact round) and bf16x2 of residual
#define CVTHILO2(fx, fy, h, l) do { \
    asm("cvt.rn.bf16x2.f32 %0, %1, %2;" : "=r"(h) : "f"(fy), "f"(fx)); \
    float _rx = (fx) - __uint_as_float((h) << 16); \
    float _ry = (fy) - __uint_as_float((h) & 0xffff0000u); \
    asm("cvt.rn.bf16x2.f32 %0, %1, %2;" : "=r"(l) : "f"(_ry), "f"(_rx)); \
} while (0)

__device__ __forceinline__ float fast_tanh(float v) {
    return 1.0f - 2.0f / (__expf(2.0f * v) + 1.0f);
}

extern __shared__ __align__(128) char smem[];

__global__ __launch_bounds__(256, 3)
void gcn_hmma_kernel(const float* __restrict__ x, float* __restrict__ out)
{
    const int tid  = threadIdx.x;
    const uint32_t sbase = (uint32_t)__cvta_generic_to_shared(smem);

    // ---- stage B hi/lo into padded smem rows (8B chunks) ----
    {
        const uint2* whi = reinterpret_cast<const uint2*>(g_Whi);
        const uint2* wlo = reinterpret_cast<const uint2*>(g_Wlo);
#pragma unroll
        for (int i = 0; i < 16; i++) {
            int idx = tid + i * 256;          // 0..4095
            int n = idx >> 6, c = idx & 63;   // 64 chunks of 4 bf16 per row
            *reinterpret_cast<uint2*>(smem + B_HI_OFF + n * BROW_B + c * 8) = whi[idx];
            *reinterpret_cast<uint2*>(smem + B_LO_OFF + n * BROW_B + c * 8) = wlo[idx];
        }
    }
    if (tid < NCOL) reinterpret_cast<float*>(smem + BIAS_OFF)[tid] = g_bias[tid];
    if (tid < HID)  reinterpret_cast<float*>(smem + WLIN_OFF)[tid] = g_wlin[tid];
    if (tid == 0)   reinterpret_cast<float*>(smem + BLIN_OFF)[0] = g_blin;
    __syncthreads();

    const int warp = tid >> 5, lane = tid & 31;
    const int g = lane >> 2, t = lane & 3;

    const int nodeBase = blockIdx.x * TILE_M + warp * 16;
    const int r0 = nodeBase + g, r1 = r0 + 8;
    const int cr0 = (r0 < N_NODES) ? r0 : (N_NODES - 1);
    const int cr1 = (r1 < N_NODES) ? r1 : (N_NODES - 1);
    const float4* p0 = reinterpret_cast<const float4*>(x) + (size_t)cr0 * 64 + t;
    const float4* p1 = reinterpret_cast<const float4*>(x) + (size_t)cr1 * 64 + t;

    // ldmatrix per-lane address (logical layout; matches permuted-stored W)
    const int lm_n = ((lane >> 4) & 1) * 8 + (lane & 7);
    const int lm_k = ((lane >> 3) & 1) * 8;
    const uint32_t lmhi = sbase + B_HI_OFF + lm_n * BROW_B + lm_k * 2;

    float acc[8][4];
#pragma unroll
    for (int i = 0; i < 8; i++)
#pragma unroll
        for (int j = 0; j < 4; j++) acc[i][j] = 0.0f;

#pragma unroll 2
    for (int ks = 0; ks < 16; ks++) {
        float4 v0 = __ldg(p0 + ks * 4);
        float4 v1 = __ldg(p1 + ks * 4);

        uint32_t ah[4], al[4];
        CVTHILO2(v0.x, v0.y, ah[0], al[0]);
        CVTHILO2(v1.x, v1.y, ah[1], al[1]);
        CVTHILO2(v0.z, v0.w, ah[2], al[2]);
        CVTHILO2(v1.z, v1.w, ah[3], al[3]);

        // keep all hi-B fragments live; three de-clustered passes so that
        // consecutive MMAs on the same accumulator are ~8 issues apart
        uint32_t bh[4][4];
#pragma unroll
        for (int nt2 = 0; nt2 < 4; nt2++)
            LDM4(bh[nt2], lmhi + nt2 * (16 * BROW_B) + ks * 32);

#pragma unroll
        for (int nt2 = 0; nt2 < 4; nt2++) {            // pass 1: hi*hi
            MMA(acc[2 * nt2],     ah, bh[nt2][0], bh[nt2][1]);
            MMA(acc[2 * nt2 + 1], ah, bh[nt2][2], bh[nt2][3]);
        }
#pragma unroll
        for (int nt2 = 0; nt2 < 4; nt2++) {            // pass 2: lo*hi (reuse bh)
            MMA(acc[2 * nt2],     al, bh[nt2][0], bh[nt2][1]);
            MMA(acc[2 * nt2 + 1], al, bh[nt2][2], bh[nt2][3]);
        }
#pragma unroll
        for (int nt2 = 0; nt2 < 4; nt2++) {            // pass 3: hi*lo
            uint32_t bl[4];
            LDM4(bl, lmhi + B_BYTES + nt2 * (16 * BROW_B) + ks * 32);
            MMA(acc[2 * nt2],     ah, bl[0], bl[1]);
            MMA(acc[2 * nt2 + 1], ah, bl[2], bl[3]);
        }
    }

    // ---- epilogue: fully register/shuffle based ----
    const float* sBias = reinterpret_cast<const float*>(smem + BIAS_OFF);
    const float* sWlin = reinterpret_cast<const float*>(smem + WLIN_OFF);
    const float  blin  = reinterpret_cast<const float*>(smem + BLIN_OFF)[0];

#pragma unroll
    for (int row = 0; row < 2; row++) {
        float s = 0.0f;
#pragma unroll
        for (int nt = 0; nt < 4; nt++) {
#pragma unroll
            for (int j = 0; j < 2; j++) {
                int c = nt * 8 + 2 * t + j;
                float zv = acc[nt][row * 2 + j]     + sBias[c];
                float hv = acc[nt + 4][row * 2 + j] + sBias[HID + c];
                float z  = 1.0f / (1.0f + __expf(-zv));
                float th = fast_tanh(hv);
                float h  = fmaxf((1.0f - z) * th, 0.0f);
                s = fmaf(h, sWlin[c], s);
            }
        }
        s += __shfl_xor_sync(0xffffffffu, s, 1);
        s += __shfl_xor_sync(0xffffffffu, s, 2);
        int node = row ? r1 : r0;
        if (t == 0 && node < N_NODES) out[node] = s + blin;
    }
}

extern "C" void kernel_launch(void* const* d_in, const int* in_sizes, int n_in,
                              void* d_out, int out_size)
{
    const float* x    = (const float*)d_in[0];
    const float* Wz   = (const float*)d_in[3];
    const float* bz   = (const float*)d_in[4];
    const float* Wh   = (const float*)d_in[7];
    const float* bh   = (const float*)d_in[8];
    const float* Wlin = (const float*)d_in[9];
    const float* blin = (const float*)d_in[10];
    float* out = (float*)d_out;

    prep_kernel<<<64, 256>>>(Wz, bz, Wh, bh, Wlin, blin);

    cudaFuncSetAttribute(gcn_hmma_kernel,
                         cudaFuncAttributeMaxDynamicSharedMemorySize, SMEM_TOTAL);
    gcn_hmma_kernel<<<NT, 256, SMEM_TOTAL>>>(x, out);
}